// round 16
// baseline (speedup 1.0000x reference)
#include <cuda_runtime.h>
#include <cuda_bf16.h>
#include <stdint.h>
#include <math.h>

// Shapes (fixed): B=4, S=2, T=1024, D=512, H=8, HD=64, M = B*S*T = 8192
// bf16 tensor-core GEMMs (mma.sync m16n8k16, fp32 accum), 2-stage cp.async.
// Projection GEMMs: 128x64 block tiles, 256 thr / 8 warps (32x32 warp tiles)
// -> 2-6x more CTAs for occupancy. Fused attention: loop1 computes z locally,
// loop2 recomputes scores, normalizes + competitive-combines on the C->A
// repack, runs AV. Q carries 0.125*log2(e) so exp is bare ex2.approx.

// ---------------- device workspaces ----------------
__device__ __nv_bfloat16 g_Xh[8192ull * 512];
__device__ __nv_bfloat16 g_Wh[4ull * 512 * 512];  // [Wq;Wk;Wv;Wo]
__device__ __nv_bfloat16 g_Qh[8192ull * 512];     // Q * 0.125 * log2(e)
__device__ __nv_bfloat16 g_Kh[8192ull * 512];
__device__ __nv_bfloat16 g_Vh[8192ull * 512];
__device__ __nv_bfloat16 g_attnh[8192ull * 512];
__device__ float         g_proj[8192ull * 512];

// ---------------- helpers ----------------
__device__ __forceinline__ uint32_t pack_bf16x2(float a, float b) {
    __nv_bfloat162 h = __floats2bfloat162_rn(a, b);
    return *reinterpret_cast<uint32_t*>(&h);
}

__device__ __forceinline__ void mma16816(float* c, const uint32_t* a, uint32_t b0, uint32_t b1) {
    asm volatile(
        "mma.sync.aligned.m16n8k16.row.col.f32.bf16.bf16.f32 "
        "{%0,%1,%2,%3}, {%4,%5,%6,%7}, {%8,%9}, {%0,%1,%2,%3};\n"
        : "+f"(c[0]), "+f"(c[1]), "+f"(c[2]), "+f"(c[3])
        : "r"(a[0]), "r"(a[1]), "r"(a[2]), "r"(a[3]), "r"(b0), "r"(b1));
}

__device__ __forceinline__ void cpa16(void* smem, const void* g) {
    uint32_t s = (uint32_t)__cvta_generic_to_shared(smem);
    asm volatile("cp.async.cg.shared.global [%0], [%1], 16;" :: "r"(s), "l"(g));
}
#define CPA_COMMIT asm volatile("cp.async.commit_group;")
#define CPA_WAIT0  asm volatile("cp.async.wait_group 0;")

__device__ __forceinline__ float rcp_approx(float x) {
    float r;
    asm("rcp.approx.f32 %0, %1;" : "=f"(r) : "f"(x));
    return r;
}

__device__ __forceinline__ float ex2f(float x) {
    float r;
    asm("ex2.approx.f32 %0, %1;" : "=f"(r) : "f"(x));
    return r;
}

__device__ __forceinline__ float blk_red_sum(float v, float* sm) {
    int lane = threadIdx.x & 31, wid = threadIdx.x >> 5;
#pragma unroll
    for (int o = 16; o; o >>= 1) v += __shfl_xor_sync(0xffffffffu, v, o);
    if (lane == 0) sm[wid] = v;
    __syncthreads();
    float r = 0.f;
#pragma unroll
    for (int i = 0; i < 8; i++) r += sm[i];
    __syncthreads();
    return r;
}

// ---------------- 0) convert inputs to bf16 ----------------
__global__ __launch_bounds__(256) void k_prep(
    const float* __restrict__ X,
    const float* __restrict__ Wq, const float* __restrict__ Wk,
    const float* __restrict__ Wv, const float* __restrict__ Wo)
{
    const int idx = blockIdx.x * 256 + threadIdx.x;
    if (idx < 1048576) {
        float4 v = ((const float4*)X)[idx];
        uint2 o; o.x = pack_bf16x2(v.x, v.y); o.y = pack_bf16x2(v.z, v.w);
        ((uint2*)g_Xh)[idx] = o;
    } else {
        int j = idx - 1048576;
        int w = j >> 16;
        const float4* src = (w == 0) ? (const float4*)Wq : (w == 1) ? (const float4*)Wk
                          : (w == 2) ? (const float4*)Wv : (const float4*)Wo;
        float4 v = src[j & 65535];
        uint2 o; o.x = pack_bf16x2(v.x, v.y); o.y = pack_bf16x2(v.z, v.w);
        ((uint2*)g_Wh)[j] = o;
    }
}

// ---------------- 1) QKV projection: 128x64 tiles, 256 thr, warp 32x32 --------
// grid (24, 64): n0g = blockIdx.x * 64 over stacked [Wq;Wk;Wv] N=1536.
__global__ __launch_bounds__(256) void k_qkv_mma(
    const float* __restrict__ bq, const float* __restrict__ bk, const float* __restrict__ bv)
{
    __shared__ __nv_bfloat16 As[2][128][40];
    __shared__ __nv_bfloat16 Bs[2][64][40];
    const int tid = threadIdx.x, lane = tid & 31, warp = tid >> 5;
    const int wm = warp >> 1, wn = warp & 1;
    const int g = lane >> 2, t = lane & 3;
    const int m0 = blockIdx.y * 128, n0g = blockIdx.x * 64;

    const int arow = tid >> 1, aseg = (tid & 1) * 16;
    const int brow = tid >> 2, bseg = (tid & 3) * 8;
    const __nv_bfloat16* srcA0 = g_Xh + (size_t)(m0 + arow) * 512 + aseg;
    const __nv_bfloat16* srcB0 = g_Wh + (size_t)(n0g + brow) * 512 + bseg;

    float acc[2][4][4] = {};

#define QKV_ISSUE(K0, BUF)                                            \
    {                                                                 \
        cpa16(&As[BUF][arow][aseg],     srcA0 + (K0));                \
        cpa16(&As[BUF][arow][aseg + 8], srcA0 + (K0) + 8);            \
        cpa16(&Bs[BUF][brow][bseg],     srcB0 + (K0));                \
    }

    QKV_ISSUE(0, 0); CPA_COMMIT;

    for (int it = 0; it < 16; it++) {
        CPA_WAIT0;
        __syncthreads();
        if (it + 1 < 16) { QKV_ISSUE((it + 1) * 32, (it + 1) & 1); CPA_COMMIT; }
        const int cb = it & 1;
#pragma unroll
        for (int kk = 0; kk < 32; kk += 16) {
            uint32_t a[2][4];
#pragma unroll
            for (int mi = 0; mi < 2; mi++)
#pragma unroll
                for (int p = 0; p < 4; p++)
                    a[mi][p] = *(const uint32_t*)&As[cb][wm * 32 + mi * 16 + ((p & 1) << 3) + g]
                                                   [kk + 2 * t + ((p >> 1) << 3)];
#pragma unroll
            for (int ni = 0; ni < 4; ni++) {
                uint32_t b0 = *(const uint32_t*)&Bs[cb][wn * 32 + ni * 8 + g][kk + 2 * t];
                uint32_t b1 = *(const uint32_t*)&Bs[cb][wn * 32 + ni * 8 + g][kk + 2 * t + 8];
#pragma unroll
                for (int mi = 0; mi < 2; mi++) mma16816(acc[mi][ni], a[mi], b0, b1);
            }
        }
        __syncthreads();
    }
#undef QKV_ISSUE

    const int mat = n0g >> 9, nloc = n0g & 511;
    const float* bias = (mat == 0) ? bq : (mat == 1) ? bk : bv;
    __nv_bfloat16* out = (mat == 0) ? g_Qh : (mat == 1) ? g_Kh : g_Vh;
    // Q scale: 1/sqrt(64) * log2(e) so attention logits are base-2 ready.
    const float scale = (mat == 0) ? 0.125f * 1.4426950408889634f : 1.0f;

#pragma unroll
    for (int mi = 0; mi < 2; mi++) {
        int r0 = m0 + wm * 32 + mi * 16 + g;
#pragma unroll
        for (int ni = 0; ni < 4; ni++) {
            int col = nloc + wn * 32 + ni * 8 + 2 * t;
            float b0f = bias[col], b1f = bias[col + 1];
            *(uint32_t*)(out + (size_t)r0 * 512 + col) =
                pack_bf16x2((acc[mi][ni][0] + b0f) * scale, (acc[mi][ni][1] + b1f) * scale);
            *(uint32_t*)(out + (size_t)(r0 + 8) * 512 + col) =
                pack_bf16x2((acc[mi][ni][2] + b0f) * scale, (acc[mi][ni][3] + b1f) * scale);
        }
    }
}

// ---------------- 2) fused attention: rowsum pass + normalize+compete+AV ------
// grid (16, 32): x = 64-row q-tile, y = bh. 128 threads = 4 warps.
__global__ __launch_bounds__(128) void k_attn_fused()
{
    __shared__ __nv_bfloat16 K1s[2][32][72];
    __shared__ __nv_bfloat16 K2s[2][32][72];
    __shared__ __nv_bfloat16 V1s[2][64][40];   // [dim][tok]
    __shared__ __nv_bfloat16 V2s[2][64][40];

    const int bh = blockIdx.y, b = bh >> 3, h = bh & 7;
    const int m0 = blockIdx.x * 64;
    const __nv_bfloat16* Q1 = g_Qh + ((size_t)(b * 2 + 0) * 1024) * 512 + h * 64;
    const __nv_bfloat16* Q2 = g_Qh + ((size_t)(b * 2 + 1) * 1024) * 512 + h * 64;
    const __nv_bfloat16* K1 = g_Kh + ((size_t)(b * 2 + 0) * 1024) * 512 + h * 64;
    const __nv_bfloat16* K2 = g_Kh + ((size_t)(b * 2 + 1) * 1024) * 512 + h * 64;
    const __nv_bfloat16* V1 = g_Vh + ((size_t)(b * 2 + 0) * 1024) * 512 + h * 64;
    const __nv_bfloat16* V2 = g_Vh + ((size_t)(b * 2 + 1) * 1024) * 512 + h * 64;
    __nv_bfloat16* C1 = g_attnh + ((size_t)(b * 2 + 0) * 1024) * 512 + h * 64;  // A12 @ V2
    __nv_bfloat16* C2 = g_attnh + ((size_t)(b * 2 + 1) * 1024) * 512 + h * 64;  // A21 @ V1

    const int tid = threadIdx.x, lane = tid & 31, warp = tid >> 5;
    const int g = lane >> 2, t = lane & 3;

    // Q A-fragments, held in registers for the whole kernel.
    uint32_t qa1[4][4], qa2[4][4];
#pragma unroll
    for (int kc = 0; kc < 4; kc++)
#pragma unroll
        for (int p = 0; p < 4; p++) {
            const int row = m0 + warp * 16 + ((p & 1) << 3) + g;
            const int col = kc * 16 + ((p >> 1) << 3) + 2 * t;
            qa1[kc][p] = *(const uint32_t*)(Q1 + (size_t)row * 512 + col);
            qa2[kc][p] = *(const uint32_t*)(Q2 + (size_t)row * 512 + col);
        }

    // K/V tile load mappings: 32 rows (tokens) x 4 segments of 16 bf16
    const int krow = tid >> 2, kseg = (tid & 3) * 16;
    const __nv_bfloat16* srcK1 = K1 + (size_t)krow * 512 + kseg;
    const __nv_bfloat16* srcK2 = K2 + (size_t)krow * 512 + kseg;
    const __nv_bfloat16* srcV1 = V1 + (size_t)krow * 512 + kseg;
    const __nv_bfloat16* srcV2 = V2 + (size_t)krow * 512 + kseg;

#define ATT_ISSUE_K(K0, BUF)                                              \
    {                                                                     \
        cpa16(&K1s[BUF][krow][kseg],     srcK1 + (size_t)(K0) * 512);     \
        cpa16(&K1s[BUF][krow][kseg + 8], srcK1 + (size_t)(K0) * 512 + 8); \
        cpa16(&K2s[BUF][krow][kseg],     srcK2 + (size_t)(K0) * 512);     \
        cpa16(&K2s[BUF][krow][kseg + 8], srcK2 + (size_t)(K0) * 512 + 8); \
    }

    // ================= loop 1: row sums z (K only) =================
    float z1a = 0.f, z1b = 0.f, z2a = 0.f, z2b = 0.f;

    ATT_ISSUE_K(0, 0); CPA_COMMIT;
    for (int it = 0; it < 32; it++) {
        CPA_WAIT0;
        __syncthreads();
        if (it + 1 < 32) { ATT_ISSUE_K((it + 1) * 32, (it + 1) & 1); CPA_COMMIT; }
        const int cb = it & 1;
#pragma unroll
        for (int nb = 0; nb < 4; nb++) {
            float c12[4] = {}, c21[4] = {};
#pragma unroll
            for (int kc = 0; kc < 4; kc++) {
                uint32_t b0 = *(const uint32_t*)&K2s[cb][nb * 8 + g][kc * 16 + 2 * t];
                uint32_t b1 = *(const uint32_t*)&K2s[cb][nb * 8 + g][kc * 16 + 2 * t + 8];
                mma16816(c12, qa1[kc], b0, b1);
                uint32_t d0 = *(const uint32_t*)&K1s[cb][nb * 8 + g][kc * 16 + 2 * t];
                uint32_t d1 = *(const uint32_t*)&K1s[cb][nb * 8 + g][kc * 16 + 2 * t + 8];
                mma16816(c21, qa2[kc], d0, d1);
            }
            z1a += ex2f(c12[0]) + ex2f(c12[1]);
            z1b += ex2f(c12[2]) + ex2f(c12[3]);
            z2a += ex2f(c21[0]) + ex2f(c21[1]);
            z2b += ex2f(c21[2]) + ex2f(c21[3]);
        }
        __syncthreads();
    }
#pragma unroll
    for (int o = 1; o < 4; o <<= 1) {
        z1a += __shfl_xor_sync(0xffffffffu, z1a, o);
        z1b += __shfl_xor_sync(0xffffffffu, z1b, o);
        z2a += __shfl_xor_sync(0xffffffffu, z2a, o);
        z2b += __shfl_xor_sync(0xffffffffu, z2b, o);
    }
    const float i1a = __fdividef(1.f, z1a), i1b = __fdividef(1.f, z1b);
    const float i2a = __fdividef(1.f, z2a), i2b = __fdividef(1.f, z2b);

    // ================= loop 2: normalize + compete + AV =================
    float o1[8][4] = {}, o2[8][4] = {};
    __nv_bfloat16 vr1[16], vr2[16];

#define ATT_LD_V(K0)                                                  \
    {                                                                 \
        const __nv_bfloat16* s1 = srcV1 + (size_t)(K0) * 512;         \
        const __nv_bfloat16* s2 = srcV2 + (size_t)(K0) * 512;         \
        *(uint4*)vr1       = *(const uint4*)s1;                       \
        *(uint4*)(vr1 + 8) = *(const uint4*)(s1 + 8);                 \
        *(uint4*)vr2       = *(const uint4*)s2;                       \
        *(uint4*)(vr2 + 8) = *(const uint4*)(s2 + 8);                 \
    }
#define ATT_ST_V(BUF)                                                 \
    {                                                                 \
        _Pragma("unroll")                                             \
        for (int j = 0; j < 16; j++) {                                \
            V1s[BUF][kseg + j][krow] = vr1[j];                        \
            V2s[BUF][kseg + j][krow] = vr2[j];                        \
        }                                                             \
    }

    ATT_ISSUE_K(0, 0); CPA_COMMIT;
    ATT_LD_V(0); ATT_ST_V(0);
    ATT_LD_V(32);

    for (int it = 0; it < 32; it++) {
        CPA_WAIT0;
        __syncthreads();
        if (it + 1 < 32) { ATT_ISSUE_K((it + 1) * 32, (it + 1) & 1); CPA_COMMIT; }
        const int cb = it & 1;

        uint32_t na1[2][4], na2[2][4];   // AV A-frags [kc2][p]
#pragma unroll
        for (int nb = 0; nb < 4; nb++) {
            float c12[4] = {}, c21[4] = {};
#pragma unroll
            for (int kc = 0; kc < 4; kc++) {
                uint32_t b0 = *(const uint32_t*)&K2s[cb][nb * 8 + g][kc * 16 + 2 * t];
                uint32_t b1 = *(const uint32_t*)&K2s[cb][nb * 8 + g][kc * 16 + 2 * t + 8];
                mma16816(c12, qa1[kc], b0, b1);
                uint32_t d0 = *(const uint32_t*)&K1s[cb][nb * 8 + g][kc * 16 + 2 * t];
                uint32_t d1 = *(const uint32_t*)&K1s[cb][nb * 8 + g][kc * 16 + 2 * t + 8];
                mma16816(c21, qa2[kc], d0, d1);
            }
            float s10 = ex2f(c12[0]) * i1a, s11 = ex2f(c12[1]) * i1a;
            float s12f = ex2f(c12[2]) * i1b, s13 = ex2f(c12[3]) * i1b;
            float s20 = ex2f(c21[0]) * i2a, s21f = ex2f(c21[1]) * i2a;
            float s22 = ex2f(c21[2]) * i2b, s23 = ex2f(c21[3]) * i2b;
            float d0 = s10 + s20 + 1e-6f, d1 = s11 + s21f + 1e-6f;
            float d2 = s12f + s22 + 1e-6f, d3 = s13 + s23 + 1e-6f;
            float ra = rcp_approx(d0 * d1);
            float rb = rcp_approx(d2 * d3);
            float inv0 = ra * d1, inv1 = ra * d0;
            float inv2 = rb * d3, inv3 = rb * d2;
            const int kc2 = nb >> 1, pb = (nb & 1) << 1;
            na1[kc2][pb]     = pack_bf16x2(s10 * inv0, s11 * inv1);
            na1[kc2][pb + 1] = pack_bf16x2(s12f * inv2, s13 * inv3);
            na2[kc2][pb]     = pack_bf16x2(s20 * inv0, s21f * inv1);
            na2[kc2][pb + 1] = pack_bf16x2(s22 * inv2, s23 * inv3);
        }

#pragma unroll
        for (int nd = 0; nd < 8; nd++) {
            const int cbase = nd * 8 + g;
#pragma unroll
            for (int kc2 = 0; kc2 < 2; kc2++) {
                uint32_t b20 = *(const uint32_t*)&V2s[cb][cbase][kc2 * 16 + 2 * t];
                uint32_t b21 = *(const uint32_t*)&V2s[cb][cbase][kc2 * 16 + 2 * t + 8];
                mma16816(o1[nd], na1[kc2], b20, b21);
                uint32_t b10 = *(const uint32_t*)&V1s[cb][cbase][kc2 * 16 + 2 * t];
                uint32_t b11 = *(const uint32_t*)&V1s[cb][cbase][kc2 * 16 + 2 * t + 8];
                mma16816(o2[nd], na2[kc2], b10, b11);
            }
        }

        if (it + 1 < 32) {
            ATT_ST_V((it + 1) & 1);
            if (it + 2 < 32) ATT_LD_V((it + 2) * 32);
        }
    }
#undef ATT_ISSUE_K
#undef ATT_LD_V
#undef ATT_ST_V

    const int r0 = m0 + warp * 16 + g;
#pragma unroll
    for (int nd = 0; nd < 8; nd++) {
        int col = nd * 8 + 2 * t;
        *(uint32_t*)(C1 + (size_t)r0 * 512 + col)       = pack_bf16x2(o1[nd][0], o1[nd][1]);
        *(uint32_t*)(C1 + (size_t)(r0 + 8) * 512 + col) = pack_bf16x2(o1[nd][2], o1[nd][3]);
        *(uint32_t*)(C2 + (size_t)r0 * 512 + col)       = pack_bf16x2(o2[nd][0], o2[nd][1]);
        *(uint32_t*)(C2 + (size_t)(r0 + 8) * 512 + col) = pack_bf16x2(o2[nd][2], o2[nd][3]);
    }
}

// ---------------- 3) output projection: 128x64 tiles, 256 thr, warp 32x32 -----
// grid (8, 64)
__global__ __launch_bounds__(256) void k_out_mma(const float* __restrict__ bo)
{
    __shared__ __nv_bfloat16 As[2][128][40];
    __shared__ __nv_bfloat16 Bs[2][64][40];
    const int tid = threadIdx.x, lane = tid & 31, warp = tid >> 5;
    const int wm = warp >> 1, wn = warp & 1;
    const int g = lane >> 2, t = lane & 3;
    const int m0 = blockIdx.y * 128, n0 = blockIdx.x * 64;
    const __nv_bfloat16* Wo = g_Wh + 3ull * 512 * 512;

    const int arow = tid >> 1, aseg = (tid & 1) * 16;
    const int brow = tid >> 2, bseg = (tid & 3) * 8;
    const __nv_bfloat16* srcA0 = g_attnh + (size_t)(m0 + arow) * 512 + aseg;
    const __nv_bfloat16* srcB0 = Wo + (size_t)(n0 + brow) * 512 + bseg;

    float acc[2][4][4] = {};

#define OUT_ISSUE(K0, BUF)                                            \
    {                                                                 \
        cpa16(&As[BUF][arow][aseg],     srcA0 + (K0));                \
        cpa16(&As[BUF][arow][aseg + 8], srcA0 + (K0) + 8);            \
        cpa16(&Bs[BUF][brow][bseg],     srcB0 + (K0));                \
    }

    OUT_ISSUE(0, 0); CPA_COMMIT;

    for (int it = 0; it < 16; it++) {
        CPA_WAIT0;
        __syncthreads();
        if (it + 1 < 16) { OUT_ISSUE((it + 1) * 32, (it + 1) & 1); CPA_COMMIT; }
        const int cb = it & 1;
#pragma unroll
        for (int kk = 0; kk < 32; kk += 16) {
            uint32_t a[2][4];
#pragma unroll
            for (int mi = 0; mi < 2; mi++)
#pragma unroll
                for (int p = 0; p < 4; p++)
                    a[mi][p] = *(const uint32_t*)&As[cb][wm * 32 + mi * 16 + ((p & 1) << 3) + g]
                                                   [kk + 2 * t + ((p >> 1) << 3)];
#pragma unroll
            for (int ni = 0; ni < 4; ni++) {
                uint32_t b0 = *(const uint32_t*)&Bs[cb][wn * 32 + ni * 8 + g][kk + 2 * t];
                uint32_t b1 = *(const uint32_t*)&Bs[cb][wn * 32 + ni * 8 + g][kk + 2 * t + 8];
#pragma unroll
                for (int mi = 0; mi < 2; mi++) mma16816(acc[mi][ni], a[mi], b0, b1);
            }
        }
        __syncthreads();
    }
#undef OUT_ISSUE

#pragma unroll
    for (int mi = 0; mi < 2; mi++) {
        int r0 = m0 + wm * 32 + mi * 16 + g;
#pragma unroll
        for (int ni = 0; ni < 4; ni++) {
            int col = n0 + wn * 32 + ni * 8 + 2 * t;
            float b0f = bo[col], b1f = bo[col + 1];
            *(float2*)(g_proj + (size_t)r0 * 512 + col) =
                make_float2(acc[mi][ni][0] + b0f, acc[mi][ni][1] + b1f);
            *(float2*)(g_proj + (size_t)(r0 + 8) * 512 + col) =
                make_float2(acc[mi][ni][2] + b0f, acc[mi][ni][3] + b1f);
        }
    }
}

// ---------------- 4) LayerNorm + gate + residual ----------------
__global__ __launch_bounds__(256) void k_ln(
    const float* __restrict__ hidden,
    const float* __restrict__ ln_g, const float* __restrict__ ln_b,
    const float* __restrict__ alpha, float* __restrict__ out)
{
    const int m = blockIdx.x;
    const int s = (m >> 10) & 1;
    const float* p = g_proj + (size_t)m * 512;
    const int tid = threadIdx.x;
    __shared__ float sm[8];

    float x0 = p[tid], x1 = p[tid + 256];
    float sum = blk_red_sum(x0 + x1, sm);
    float sq  = blk_red_sum(x0 * x0 + x1 * x1, sm);
    float mu  = sum * (1.f / 512.f);
    float var = sq * (1.f / 512.f) - mu * mu;
    float rstd = rsqrtf(var + 1e-5f);
    float al = alpha[s];
    size_t base = (size_t)m * 512;

    {
        int e = tid;
        float y = (x0 - mu) * rstd * ln_g[s * 512 + e] + ln_b[s * 512 + e];
        out[base + e] = hidden[base + e] + y * al;
    }
    {
        int e = tid + 256;
        float y = (x1 - mu) * rstd * ln_g[s * 512 + e] + ln_b[s * 512 + e];
        out[base + e] = hidden[base + e] + y * al;
    }
}

// ---------------- launch ----------------
extern "C" void kernel_launch(void* const* d_in, const int* in_sizes, int n_in,
                              void* d_out, int out_size)
{
    const float* hidden = (const float*)d_in[0];
    const float* Wq = (const float*)d_in[1];  const float* bq = (const float*)d_in[2];
    const float* Wk = (const float*)d_in[3];  const float* bk = (const float*)d_in[4];
    const float* Wv = (const float*)d_in[5];  const float* bv = (const float*)d_in[6];
    const float* Wo = (const float*)d_in[7];  const float* bo = (const float*)d_in[8];
    const float* lng = (const float*)d_in[9]; const float* lnb = (const float*)d_in[10];
    const float* alpha = (const float*)d_in[11];
    float* out = (float*)d_out;

    k_prep<<<5120, 256>>>(hidden, Wq, Wk, Wv, Wo);
    k_qkv_mma<<<dim3(24, 64), 256>>>(bq, bk, bv);
    k_attn_fused<<<dim3(16, 32), 128>>>();
    k_out_mma<<<dim3(8, 64), 256>>>(bo);
    k_ln<<<8192, 256>>>(hidden, lng, lnb, alpha, out);
}